// round 5
// baseline (speedup 1.0000x reference)
#include <cuda_runtime.h>
#include <math.h>

typedef unsigned long long ull;

#define T_ 1024
#define B_ 16
#define E_ 1024
#define H_ 512
#define C_ 1024
#define L_ 6
#define M_ (T_*B_)
#define NG 4096
#define KI 1024

// ------------------------ device scratch ------------------------
__device__ float g_xbuf[2][(size_t)M_*C_];   // ping-pong activations [m][1024], m = t*16+b
__device__ float g_G[(size_t)M_*NG];         // input-projected gates [m][4096]
__device__ float g_W5[5*E_*C_];              // conv weights [kk][c], kk = dk*1024+e
__device__ float g_WihT[3][(size_t)KI*NG];   // Wih^T packed [k][dir*2048 + r]
__device__ float g_biasG[3][NG];             // bih+bhh packed
__device__ float g_bnA[C_], g_bnB[C_];       // fused BN scale / (bias incl conv_b)
__device__ float g_h[2][2][H_*B_];           // h state [dir][parity][b*512 + j]
__device__ unsigned g_cnt[2][T_];            // per-step barrier counters
__device__ float g_logits[M_*L_];

// ------------------------ f32x2 helpers ------------------------
__device__ __forceinline__ ull pk2(float x){ ull r; asm("mov.b64 %0,{%1,%1};" : "=l"(r) : "f"(x)); return r; }
__device__ __forceinline__ void fma2(ull& a, ull x, ull y){ asm("fma.rn.f32x2 %0, %1, %2, %0;" : "+l"(a) : "l"(x), "l"(y)); }
__device__ __forceinline__ float2 up2(ull a){ float2 f; asm("mov.b64 {%0,%1}, %2;" : "=f"(f.x), "=f"(f.y) : "l"(a)); return f; }
__device__ __forceinline__ float sigf(float x){ return 1.f/(1.f + expf(-x)); }

// ------------------------ pack kernels ------------------------
__global__ void k_pack_w5(const float* __restrict__ cw){
    int idx = blockIdx.x*256 + threadIdx.x;            // < 5120*1024
    int c  = idx & (C_-1);
    int kk = idx >> 10;
    int e  = kk & (E_-1);
    int dk = kk >> 10;
    g_W5[idx] = cw[((size_t)c*E_ + e)*5 + dk];
}

__global__ void k_pack_wih(const float* __restrict__ wih){
    int idx = blockIdx.x*256 + threadIdx.x;            // < 3*1024*4096
    int n = idx & (NG-1);
    int k = (idx >> 12) & (KI-1);
    int l = idx >> 22;
    int dir = n >> 11, r = n & 2047;
    ((float*)g_WihT)[idx] = wih[(((size_t)(l*2+dir))*2048 + r)*KI + k];
}

__global__ void k_pack_small(const float* __restrict__ bih, const float* __restrict__ bhh,
                             const float* __restrict__ gamma, const float* __restrict__ beta,
                             const float* __restrict__ mean, const float* __restrict__ var,
                             const float* __restrict__ convb){
    int idx = blockIdx.x*256 + threadIdx.x;
    if (idx < 3*NG){
        int l = idx / NG; int n = idx - l*NG;
        int dir = n >> 11, r = n & 2047;
        int src = (l*2+dir)*2048 + r;
        ((float*)g_biasG)[idx] = bih[src] + bhh[src];
    }
    if (idx < C_){
        float s = gamma[idx] * rsqrtf(var[idx] + 1e-5f);
        g_bnA[idx] = s;
        g_bnB[idx] = s*convb[idx] + beta[idx] - mean[idx]*s;
    }
}

__global__ void k_reset(){
    int idx = blockIdx.x*256 + threadIdx.x;
    if (idx < 2*2*H_*B_) ((float*)g_h)[idx] = 0.f;
    if (idx < 2*T_) ((unsigned*)g_cnt)[idx] = 0u;
}

#define FMAROW(i, aval) { ull av = pk2(aval); \
    fma2(acc[i][0],av,b0.x); fma2(acc[i][1],av,b0.y); \
    fma2(acc[i][2],av,b1.x); fma2(acc[i][3],av,b1.y); }

// ------------------------ conv-as-GEMM + BN + ReLU ------------------------
// out[m][c] = relu(bnA[c]*(sum_kk A[m,kk]*W5[kk,c]) + bnB[c]),  A[m,kk]=emb[b, t+dk-2, e]
__global__ void __launch_bounds__(256) k_conv(const float* __restrict__ emb){
    __shared__ float As[8][128];
    __shared__ float Bs[8][128];
    int tid = threadIdx.x;
    int m0 = blockIdx.y*128, n0 = blockIdx.x*128;
    int arow = tid>>1, acol = (tid&1)*4;
    int brow = tid>>5, bcol = (tid&31)*4;
    int m = m0 + arow; int t = m>>4, b = m&15;
    const float* Bp = g_W5 + (size_t)brow*C_ + n0 + bcol;

    auto fetchA = [&](int kt)->float4{
        int kk = kt*8 + acol;
        int dk = kk >> 10, e = kk & 1023;
        int tp = t + dk - 2;
        if ((unsigned)tp < 1024u)
            return *(const float4*)(emb + ((size_t)b*1024 + tp)*1024 + e);
        return make_float4(0.f,0.f,0.f,0.f);
    };
    float4 aP = fetchA(0);
    float4 bP = *(const float4*)Bp;
    ull acc[8][4];
    #pragma unroll
    for (int i=0;i<8;i++){ acc[i][0]=0ULL; acc[i][1]=0ULL; acc[i][2]=0ULL; acc[i][3]=0ULL; }
    int tx = tid&15, ty = tid>>4;

    for (int kt=0; kt<640; ++kt){
        As[acol+0][arow]=aP.x; As[acol+1][arow]=aP.y; As[acol+2][arow]=aP.z; As[acol+3][arow]=aP.w;
        *(float4*)&Bs[brow][bcol] = bP;
        __syncthreads();
        if (kt+1 < 640){ aP = fetchA(kt+1); bP = *(const float4*)(Bp + (size_t)(kt+1)*8*C_); }
        #pragma unroll
        for (int k=0;k<8;k++){
            float4 a0 = *(const float4*)&As[k][ty*4];
            float4 a1 = *(const float4*)&As[k][64+ty*4];
            ulonglong2 b0 = *(const ulonglong2*)&Bs[k][tx*4];
            ulonglong2 b1 = *(const ulonglong2*)&Bs[k][64+tx*4];
            FMAROW(0, a0.x); FMAROW(1, a0.y); FMAROW(2, a0.z); FMAROW(3, a0.w);
            FMAROW(4, a1.x); FMAROW(5, a1.y); FMAROW(6, a1.z); FMAROW(7, a1.w);
        }
        __syncthreads();
    }
    float* xo = g_xbuf[0];
    int c0 = n0 + tx*4;
    float4 A0 = *(const float4*)&g_bnA[c0];    float4 Bb0 = *(const float4*)&g_bnB[c0];
    float4 A1 = *(const float4*)&g_bnA[c0+64]; float4 Bb1 = *(const float4*)&g_bnB[c0+64];
    #pragma unroll
    for (int i=0;i<8;i++){
        int mr = m0 + (i<4 ? ty*4+i : 64+ty*4+(i-4));
        float2 p0=up2(acc[i][0]), p1=up2(acc[i][1]), p2=up2(acc[i][2]), p3=up2(acc[i][3]);
        float4 v0 = make_float4(fmaxf(p0.x*A0.x+Bb0.x,0.f), fmaxf(p0.y*A0.y+Bb0.y,0.f),
                                fmaxf(p1.x*A0.z+Bb0.z,0.f), fmaxf(p1.y*A0.w+Bb0.w,0.f));
        float4 v1 = make_float4(fmaxf(p2.x*A1.x+Bb1.x,0.f), fmaxf(p2.y*A1.y+Bb1.y,0.f),
                                fmaxf(p3.x*A1.z+Bb1.z,0.f), fmaxf(p3.y*A1.w+Bb1.w,0.f));
        *(float4*)&xo[(size_t)mr*1024 + c0] = v0;
        *(float4*)&xo[(size_t)mr*1024 + c0+64] = v1;
    }
}

// ------------------------ LSTM input projection GEMM ------------------------
// G[m][n] = sum_k X[m][k]*WihT[k][n] + biasG[n];  X = g_xbuf[inparity]
__global__ void __launch_bounds__(256) k_gemm_gates(int layer, int inparity){
    __shared__ float As[8][128];
    __shared__ float Bs[8][128];
    int tid = threadIdx.x;
    int m0 = blockIdx.y*128, n0 = blockIdx.x*128;
    int arow = tid>>1, acol = (tid&1)*4;
    int brow = tid>>5, bcol = (tid&31)*4;
    const float* X = g_xbuf[inparity];
    const float* W = g_WihT[layer];
    const float* Ap = X + (size_t)(m0+arow)*KI + acol;
    const float* Bp = W + (size_t)brow*NG + n0 + bcol;
    float4 aP = *(const float4*)Ap;
    float4 bP = *(const float4*)Bp;
    ull acc[8][4];
    #pragma unroll
    for (int i=0;i<8;i++){ acc[i][0]=0ULL; acc[i][1]=0ULL; acc[i][2]=0ULL; acc[i][3]=0ULL; }
    int tx = tid&15, ty = tid>>4;

    for (int kt=0; kt<128; ++kt){
        As[acol+0][arow]=aP.x; As[acol+1][arow]=aP.y; As[acol+2][arow]=aP.z; As[acol+3][arow]=aP.w;
        *(float4*)&Bs[brow][bcol] = bP;
        __syncthreads();
        if (kt+1 < 128){ aP = *(const float4*)(Ap + (kt+1)*8); bP = *(const float4*)(Bp + (size_t)(kt+1)*8*NG); }
        #pragma unroll
        for (int k=0;k<8;k++){
            float4 a0 = *(const float4*)&As[k][ty*4];
            float4 a1 = *(const float4*)&As[k][64+ty*4];
            ulonglong2 b0 = *(const ulonglong2*)&Bs[k][tx*4];
            ulonglong2 b1 = *(const ulonglong2*)&Bs[k][64+tx*4];
            FMAROW(0, a0.x); FMAROW(1, a0.y); FMAROW(2, a0.z); FMAROW(3, a0.w);
            FMAROW(4, a1.x); FMAROW(5, a1.y); FMAROW(6, a1.z); FMAROW(7, a1.w);
        }
        __syncthreads();
    }
    int c0 = n0 + tx*4;
    float4 q0 = *(const float4*)&g_biasG[layer][c0];
    float4 q1 = *(const float4*)&g_biasG[layer][c0+64];
    #pragma unroll
    for (int i=0;i<8;i++){
        int mr = m0 + (i<4 ? ty*4+i : 64+ty*4+(i-4));
        float2 p0=up2(acc[i][0]), p1=up2(acc[i][1]), p2=up2(acc[i][2]), p3=up2(acc[i][3]);
        float4 v0 = make_float4(p0.x+q0.x, p0.y+q0.y, p1.x+q0.z, p1.y+q0.w);
        float4 v1 = make_float4(p2.x+q1.x, p2.y+q1.y, p3.x+q1.z, p3.y+q1.w);
        *(float4*)&g_G[(size_t)mr*NG + c0] = v0;
        *(float4*)&g_G[(size_t)mr*NG + c0+64] = v1;
    }
}

// ------------------------ persistent BiLSTM recurrence ------------------------
// 128 blocks: blocks [0,64) = forward dir, [64,128) = backward.
// Block owns h-indices [bid*8, bid*8+8): gate rows {g*512 + j}.
#define SH_STRIDE 516
__global__ void __launch_bounds__(256) k_recur(const float* __restrict__ whh, int layer, int outparity){
    extern __shared__ float smem[];
    float* sW = smem;                         // 32 rows x SH_STRIDE
    float* sH = sW + 32*SH_STRIDE;            // 16 rows x SH_STRIDE
    float* sG = sH + 16*SH_STRIDE;            // [4][8][16]
    float* sC = sG + 512;                     // [8][16]
    int tid = threadIdx.x;
    int dir = blockIdx.x >> 6;
    int bid = blockIdx.x & 63;
    int j0 = bid*8;

    // load Whh slice: rows (g*8+jj) -> whh row g*512 + j0 + jj
    for (int i = tid; i < 32*128; i += 256){
        int row = i >> 7, k4 = (i & 127)*4;
        int g = row >> 3, jj = row & 7;
        *(float4*)&sW[row*SH_STRIDE + k4] =
            *(const float4*)&whh[(((size_t)(layer*2+dir))*2048 + g*512 + j0 + jj)*512 + k4];
    }
    if (tid < 128) sC[tid] = 0.f;
    __syncthreads();

    int o  = tid;
    int g0 = o >> 7, jj = (o >> 4) & 7, b = o & 15;
    int g1 = g0 + 2;
    float* xout = g_xbuf[outparity];
    unsigned* cnt = &g_cnt[dir][0];

    for (int s = 0; s < T_; ++s){
        const float* hin = g_h[dir][s & 1];
        for (int i = tid; i < 2048; i += 256){
            int bb = i >> 7, k4 = (i & 127)*4;
            *(float4*)&sH[bb*SH_STRIDE + k4] = __ldcg((const float4*)&hin[bb*512 + k4]);
        }
        __syncthreads();

        int t = dir ? (T_-1 - s) : s;
        size_t gb = (size_t)(t*16 + b)*NG + (size_t)dir*2048;
        float acc0 = g_G[gb + g0*512 + j0 + jj];
        float acc1 = g_G[gb + g1*512 + j0 + jj];
        const float* hv = &sH[b*SH_STRIDE];
        const float* w0 = &sW[(g0*8+jj)*SH_STRIDE];
        const float* w1 = &sW[(g1*8+jj)*SH_STRIDE];
        #pragma unroll 4
        for (int k = 0; k < 512; k += 4){
            float4 h4 = *(const float4*)&hv[k];
            float4 a4 = *(const float4*)&w0[k];
            float4 c4 = *(const float4*)&w1[k];
            acc0 += a4.x*h4.x; acc1 += c4.x*h4.x;
            acc0 += a4.y*h4.y; acc1 += c4.y*h4.y;
            acc0 += a4.z*h4.z; acc1 += c4.z*h4.z;
            acc0 += a4.w*h4.w; acc1 += c4.w*h4.w;
        }
        sG[(g0*8+jj)*16 + b] = acc0;
        sG[(g1*8+jj)*16 + b] = acc1;
        __syncthreads();

        if (tid < 128){
            int jj2 = tid >> 4, b2 = tid & 15;
            float gi = sG[(0*8+jj2)*16+b2];
            float gf = sG[(1*8+jj2)*16+b2];
            float gg = sG[(2*8+jj2)*16+b2];
            float go = sG[(3*8+jj2)*16+b2];
            float c = sigf(gf)*sC[jj2*16+b2] + sigf(gi)*tanhf(gg);
            sC[jj2*16+b2] = c;
            float h = sigf(go)*tanhf(c);
            g_h[dir][(s+1)&1][b2*512 + j0 + jj2] = h;
            int t2 = dir ? (T_-1 - s) : s;
            xout[(size_t)(t2*16 + b2)*1024 + dir*512 + j0 + jj2] = h;
            __threadfence();
        }
        __syncthreads();
        if (tid == 0){
            atomicAdd(&cnt[s], 1u);
            while (atomicAdd(&cnt[s], 0u) < 64u) { }
            __threadfence();
        }
        __syncthreads();
    }
}

// ------------------------ classifier ------------------------
__global__ void __launch_bounds__(256) k_cls(const float* __restrict__ cls_w,
                                             const float* __restrict__ cls_b, int parity){
    __shared__ float sW[L_][1024];
    __shared__ float sB[L_];
    int tid = threadIdx.x;
    for (int i = tid; i < L_*1024; i += 256) ((float*)sW)[i] = cls_w[i];
    if (tid < L_) sB[tid] = cls_b[tid];
    __syncthreads();
    int m = blockIdx.x*256 + tid;
    const float* xr = &g_xbuf[parity][(size_t)m*1024];
    float acc[L_];
    #pragma unroll
    for (int l=0;l<L_;l++) acc[l] = sB[l];
    for (int k = 0; k < 1024; k += 4){
        float4 xv = *(const float4*)&xr[k];
        #pragma unroll
        for (int l=0;l<L_;l++){
            float4 wv = *(const float4*)&sW[l][k];
            acc[l] += xv.x*wv.x + xv.y*wv.y + xv.z*wv.z + xv.w*wv.w;
        }
    }
    #pragma unroll
    for (int l=0;l<L_;l++) g_logits[m*L_ + l] = acc[l];
}

// ------------------------ CRF NLL (one block) ------------------------
__global__ void __launch_bounds__(128) k_crf(const int* __restrict__ att, const int* __restrict__ lab,
                                             const float* __restrict__ startv, const float* __restrict__ endv,
                                             const float* __restrict__ trans, float* __restrict__ out){
    __shared__ float sT[36], sS[6], sE[6];
    __shared__ float sAl[16][6];
    __shared__ float sNum[16], sLoss[16];
    int tid = threadIdx.x;
    if (tid < 36) sT[tid] = trans[tid];
    if (tid < 6){ sS[tid] = startv[tid]; sE[tid] = endv[tid]; }
    __syncthreads();

    bool isDen = tid < 96;
    bool isNum = (tid >= 96) && (tid < 112);
    int b = isDen ? tid/6 : tid-96;
    int j = tid % 6;

    float score = 0.f; int prev = 0;
    if (isDen){
        sAl[b][j] = sS[j] + g_logits[b*L_ + j];     // t=0, m=b
    }
    if (isNum){
        int l0 = lab[b*T_];
        int t0 = (l0 == -100) ? 0 : l0;
        score = sS[t0] + g_logits[b*L_ + t0];
        prev = t0;
    }
    __syncthreads();

    for (int t = 1; t < T_; ++t){
        float nxt = 0.f; bool mk = false;
        if (isDen){
            mk = (att[b*T_ + t] != 0) && (lab[b*T_ + t] != -100);
            float e = g_logits[(t*16 + b)*L_ + j];
            float mx = -1e30f;
            #pragma unroll
            for (int i2=0;i2<6;i2++) mx = fmaxf(mx, sAl[b][i2] + sT[i2*6+j]);
            float ss = 0.f;
            #pragma unroll
            for (int i2=0;i2<6;i2++) ss += expf(sAl[b][i2] + sT[i2*6+j] - mx);
            nxt = mx + logf(ss) + e;
        } else if (isNum){
            int lb = lab[b*T_ + t];
            bool m = (att[b*T_ + t] != 0) && (lb != -100);
            int tt = (lb == -100) ? 0 : lb;
            if (m){
                score += sT[prev*6 + tt] + g_logits[(t*16 + b)*L_ + tt];
                prev = tt;
            }
        }
        __syncthreads();
        if (isDen && mk) sAl[b][j] = nxt;
        __syncthreads();
    }

    if (isNum) sNum[b] = score + sE[prev];
    __syncthreads();
    if (tid < 16){
        float mx = -1e30f;
        #pragma unroll
        for (int jj=0;jj<6;jj++) mx = fmaxf(mx, sAl[tid][jj] + sE[jj]);
        float ss = 0.f;
        #pragma unroll
        for (int jj=0;jj<6;jj++) ss += expf(sAl[tid][jj] + sE[jj] - mx);
        float den = mx + logf(ss);
        sLoss[tid] = den - sNum[tid];
    }
    __syncthreads();
    if (tid == 0){
        float s = 0.f;
        for (int i=0;i<16;i++) s += sLoss[i];
        out[0] = s / 16.f;
    }
}

// ------------------------ launch ------------------------
extern "C" void kernel_launch(void* const* d_in, const int* in_sizes, int n_in,
                              void* d_out, int out_size){
    const float* emb    = (const float*)d_in[0];
    const int*   att    = (const int*)  d_in[1];
    const int*   lab    = (const int*)  d_in[2];
    const float* conv_w = (const float*)d_in[3];
    const float* conv_b = (const float*)d_in[4];
    const float* bn_g   = (const float*)d_in[5];
    const float* bn_b   = (const float*)d_in[6];
    const float* bn_m   = (const float*)d_in[7];
    const float* bn_v   = (const float*)d_in[8];
    const float* wih    = (const float*)d_in[9];
    const float* whh    = (const float*)d_in[10];
    const float* bih    = (const float*)d_in[11];
    const float* bhh    = (const float*)d_in[12];
    const float* cls_w  = (const float*)d_in[13];
    const float* cls_b  = (const float*)d_in[14];
    const float* crf_s  = (const float*)d_in[15];
    const float* crf_e  = (const float*)d_in[16];
    const float* crf_t  = (const float*)d_in[17];
    float* out = (float*)d_out;

    const int RECUR_SMEM = (32*SH_STRIDE + 16*SH_STRIDE + 512 + 128) * 4;
    cudaFuncSetAttribute(k_recur, cudaFuncAttributeMaxDynamicSharedMemorySize, RECUR_SMEM);

    k_pack_w5   <<<5*E_*C_/256, 256>>>(conv_w);
    k_pack_wih  <<<3*KI*NG/256, 256>>>(wih);
    k_pack_small<<<48, 256>>>(bih, bhh, bn_g, bn_b, bn_m, bn_v, conv_b);

    k_conv<<<dim3(C_/128, M_/128), 256>>>(emb);

    for (int l = 0; l < 3; ++l){
        int inpar  = l & 1;
        int outpar = (l + 1) & 1;
        k_gemm_gates<<<dim3(NG/128, M_/128), 256>>>(l, inpar);
        k_reset<<<128, 256>>>();
        k_recur<<<128, 256, RECUR_SMEM>>>(whh, l, outpar);
    }

    k_cls<<<M_/256, 256>>>(cls_w, cls_b, 1);
    k_crf<<<1, 128>>>(att, lab, crf_s, crf_e, crf_t, out);
}

// round 6
// speedup vs baseline: 1.0075x; 1.0075x over previous
#include <cuda_runtime.h>
#include <math.h>

typedef unsigned long long ull;

#define T_ 1024
#define B_ 16
#define E_ 1024
#define H_ 512
#define C_ 1024
#define L_ 6
#define M_ (T_*B_)
#define NG 4096
#define KI 1024

// ------------------------ device scratch ------------------------
__device__ float g_xbuf[2][(size_t)M_*C_];   // ping-pong activations [m][1024], m = t*16+b
__device__ float g_G[(size_t)M_*NG];         // input-projected gates [m][4096]
__device__ float g_W5[5*E_*C_];              // conv weights [kk][c], kk = dk*1024+e
__device__ float g_WihT[3][(size_t)KI*NG];   // Wih^T packed [k][dir*2048 + r]
__device__ float g_biasG[3][NG];             // bih+bhh packed
__device__ float g_bnA[C_], g_bnB[C_];       // fused BN scale / bias(incl conv_b)
__device__ float g_h[2][2][H_*B_];           // h state [dir][parity][b*512 + j]
__device__ unsigned g_cnt[2][T_];            // per-step barrier counters
__device__ float g_logits[M_*L_];

// ------------------------ f32x2 helpers ------------------------
__device__ __forceinline__ ull pk2(float x){ ull r; asm("mov.b64 %0,{%1,%1};" : "=l"(r) : "f"(x)); return r; }
__device__ __forceinline__ void fma2(ull& a, ull x, ull y){ asm("fma.rn.f32x2 %0, %1, %2, %0;" : "+l"(a) : "l"(x), "l"(y)); }
__device__ __forceinline__ float2 up2(ull a){ float2 f; asm("mov.b64 {%0,%1}, %2;" : "=f"(f.x), "=f"(f.y) : "l"(a)); return f; }
__device__ __forceinline__ float sigf(float x){ return 1.f/(1.f + expf(-x)); }

// ------------------------ pack kernels ------------------------
__global__ void k_pack_w5(const float* __restrict__ cw){
    int idx = blockIdx.x*256 + threadIdx.x;            // < 5120*1024
    int c  = idx & (C_-1);
    int kk = idx >> 10;
    int e  = kk & (E_-1);
    int dk = kk >> 10;
    g_W5[idx] = cw[((size_t)c*E_ + e)*5 + dk];
}

__global__ void k_pack_wih(const float* __restrict__ wih){
    int idx = blockIdx.x*256 + threadIdx.x;            // < 3*1024*4096
    int n = idx & (NG-1);
    int k = (idx >> 12) & (KI-1);
    int l = idx >> 22;
    int dir = n >> 11, r = n & 2047;
    ((float*)g_WihT)[idx] = wih[(((size_t)(l*2+dir))*2048 + r)*KI + k];
}

__global__ void k_pack_small(const float* __restrict__ bih, const float* __restrict__ bhh,
                             const float* __restrict__ gamma, const float* __restrict__ beta,
                             const float* __restrict__ mean, const float* __restrict__ var,
                             const float* __restrict__ convb){
    int idx = blockIdx.x*256 + threadIdx.x;
    if (idx < 3*NG){
        int l = idx / NG; int n = idx - l*NG;
        int dir = n >> 11, r = n & 2047;
        int src = (l*2+dir)*2048 + r;
        ((float*)g_biasG)[idx] = bih[src] + bhh[src];
    }
    if (idx < C_){
        float s = gamma[idx] * rsqrtf(var[idx] + 1e-5f);
        g_bnA[idx] = s;
        g_bnB[idx] = s*convb[idx] + beta[idx] - mean[idx]*s;
    }
}

__global__ void k_reset(){
    int idx = blockIdx.x*256 + threadIdx.x;
    if (idx < 2*2*H_*B_) ((float*)g_h)[idx] = 0.f;
    if (idx < 2*T_) ((unsigned*)g_cnt)[idx] = 0u;
}

// fma2 row macro: av = duplicated A pair, b0v/b1v = column-pair ulls
#define ROWF(i, av) { fma2(acc[i][0],av,b0v.x); fma2(acc[i][1],av,b0v.y); \
                      fma2(acc[i][2],av,b1v.x); fma2(acc[i][3],av,b1v.y); }

#define GEMM_INNER(buf) \
    _Pragma("unroll") \
    for (int k = 0; k < 8; k++){ \
        ulonglong2 aA = *(const ulonglong2*)&As2[buf][k][ty*8]; \
        ulonglong2 aB = *(const ulonglong2*)&As2[buf][k][ty*8+4]; \
        ulonglong2 aC = *(const ulonglong2*)&As2[buf][k][128+ty*8]; \
        ulonglong2 aD = *(const ulonglong2*)&As2[buf][k][128+ty*8+4]; \
        ulonglong2 b0v = *(const ulonglong2*)&Bs[buf][k][tx*4]; \
        ulonglong2 b1v = *(const ulonglong2*)&Bs[buf][k][64+tx*4]; \
        ROWF(0, aA.x) ROWF(1, aA.y) ROWF(2, aB.x) ROWF(3, aB.y) \
        ROWF(4, aC.x) ROWF(5, aC.y) ROWF(6, aD.x) ROWF(7, aD.y) \
    }

#define GEMM_STORE(buf) { \
    *(ull*)&As2[buf][acol+0][2*arow] = pk2(aP.x); \
    *(ull*)&As2[buf][acol+1][2*arow] = pk2(aP.y); \
    *(ull*)&As2[buf][acol+2][2*arow] = pk2(aP.z); \
    *(ull*)&As2[buf][acol+3][2*arow] = pk2(aP.w); \
    *(float4*)&Bs[buf][brow][bcol] = bP; }

// ------------------------ conv-as-GEMM + BN + ReLU ------------------------
__global__ void __launch_bounds__(256,2) k_conv(const float* __restrict__ emb){
    __shared__ float As2[2][8][256];
    __shared__ float Bs[2][8][128];
    int tid = threadIdx.x;
    int m0 = blockIdx.y*128, n0 = blockIdx.x*128;
    int arow = tid>>1, acol = (tid&1)*4;
    int brow = tid>>5, bcol = (tid&31)*4;
    int m = m0 + arow; int t = m>>4, b = m&15;
    const float* Bp = g_W5 + (size_t)brow*C_ + n0 + bcol;

    auto fetchA = [&](int kt)->float4{
        int kk = kt*8 + acol;
        int dk = kk >> 10, e = kk & 1023;
        int tp = t + dk - 2;
        if ((unsigned)tp < 1024u)
            return *(const float4*)(emb + ((size_t)b*1024 + tp)*1024 + e);
        return make_float4(0.f,0.f,0.f,0.f);
    };
    float4 aP = fetchA(0);
    float4 bP = *(const float4*)Bp;
    ull acc[8][4];
    #pragma unroll
    for (int i=0;i<8;i++){ acc[i][0]=0ULL; acc[i][1]=0ULL; acc[i][2]=0ULL; acc[i][3]=0ULL; }
    int tx = tid&15, ty = tid>>4;
    GEMM_STORE(0);
    __syncthreads();

    for (int kt=0; kt<640; ++kt){
        int buf = kt & 1;
        if (kt+1 < 640){ aP = fetchA(kt+1); bP = *(const float4*)(Bp + (size_t)(kt+1)*8*C_); }
        GEMM_INNER(buf);
        if (kt+1 < 640){ GEMM_STORE(buf^1); }
        __syncthreads();
    }
    float* xo = g_xbuf[0];
    int c0 = n0 + tx*4;
    float4 A0 = *(const float4*)&g_bnA[c0];    float4 Bb0 = *(const float4*)&g_bnB[c0];
    float4 A1 = *(const float4*)&g_bnA[c0+64]; float4 Bb1 = *(const float4*)&g_bnB[c0+64];
    #pragma unroll
    for (int i=0;i<8;i++){
        int mr = m0 + (i<4 ? ty*4+i : 64+ty*4+(i-4));
        float2 p0=up2(acc[i][0]), p1=up2(acc[i][1]), p2=up2(acc[i][2]), p3=up2(acc[i][3]);
        float4 v0 = make_float4(fmaxf(p0.x*A0.x+Bb0.x,0.f), fmaxf(p0.y*A0.y+Bb0.y,0.f),
                                fmaxf(p1.x*A0.z+Bb0.z,0.f), fmaxf(p1.y*A0.w+Bb0.w,0.f));
        float4 v1 = make_float4(fmaxf(p2.x*A1.x+Bb1.x,0.f), fmaxf(p2.y*A1.y+Bb1.y,0.f),
                                fmaxf(p3.x*A1.z+Bb1.z,0.f), fmaxf(p3.y*A1.w+Bb1.w,0.f));
        *(float4*)&xo[(size_t)mr*1024 + c0] = v0;
        *(float4*)&xo[(size_t)mr*1024 + c0+64] = v1;
    }
}

// ------------------------ LSTM input projection GEMM ------------------------
__global__ void __launch_bounds__(256,2) k_gemm_gates(int layer, int inparity){
    __shared__ float As2[2][8][256];
    __shared__ float Bs[2][8][128];
    int tid = threadIdx.x;
    int m0 = blockIdx.y*128, n0 = blockIdx.x*128;
    int arow = tid>>1, acol = (tid&1)*4;
    int brow = tid>>5, bcol = (tid&31)*4;
    const float* Ap = g_xbuf[inparity] + (size_t)(m0+arow)*KI + acol;
    const float* Bp = g_WihT[layer] + (size_t)brow*NG + n0 + bcol;
    float4 aP = *(const float4*)Ap;
    float4 bP = *(const float4*)Bp;
    ull acc[8][4];
    #pragma unroll
    for (int i=0;i<8;i++){ acc[i][0]=0ULL; acc[i][1]=0ULL; acc[i][2]=0ULL; acc[i][3]=0ULL; }
    int tx = tid&15, ty = tid>>4;
    GEMM_STORE(0);
    __syncthreads();

    for (int kt=0; kt<128; ++kt){
        int buf = kt & 1;
        if (kt+1 < 128){ aP = *(const float4*)(Ap + (kt+1)*8); bP = *(const float4*)(Bp + (size_t)(kt+1)*8*NG); }
        GEMM_INNER(buf);
        if (kt+1 < 128){ GEMM_STORE(buf^1); }
        __syncthreads();
    }
    int c0 = n0 + tx*4;
    float4 q0 = *(const float4*)&g_biasG[layer][c0];
    float4 q1 = *(const float4*)&g_biasG[layer][c0+64];
    #pragma unroll
    for (int i=0;i<8;i++){
        int mr = m0 + (i<4 ? ty*4+i : 64+ty*4+(i-4));
        float2 p0=up2(acc[i][0]), p1=up2(acc[i][1]), p2=up2(acc[i][2]), p3=up2(acc[i][3]);
        float4 v0 = make_float4(p0.x+q0.x, p0.y+q0.y, p1.x+q0.z, p1.y+q0.w);
        float4 v1 = make_float4(p2.x+q1.x, p2.y+q1.y, p3.x+q1.z, p3.y+q1.w);
        *(float4*)&g_G[(size_t)mr*NG + c0] = v0;
        *(float4*)&g_G[(size_t)mr*NG + c0+64] = v1;
    }
}

// ------------------------ persistent BiLSTM recurrence ------------------------
// 128 blocks: [0,64)=fw, [64,128)=bw. Block owns h-indices [bid*8, bid*8+8).
// Thread mapping: r = tid>>3 in [0,32) (gate rows g*8+jj), bp = tid&7,
// handles batches bp and bp+8 (stride-8 pairing => conflict-free h loads).
#define SH_STRIDE 516
__global__ void __launch_bounds__(256) k_recur(const float* __restrict__ whh, int layer, int outparity){
    extern __shared__ float smem[];
    float* sW = smem;                         // 32 rows x SH_STRIDE
    float* sH = sW + 32*SH_STRIDE;            // 16 rows x SH_STRIDE
    float* sG = sH + 16*SH_STRIDE;            // [32 rows][16 b]
    float* sC = sG + 512;                     // [8][16]
    int tid = threadIdx.x;
    int dir = blockIdx.x >> 6;
    int bid = blockIdx.x & 63;
    int j0 = bid*8;

    for (int i = tid; i < 32*128; i += 256){
        int row = i >> 7, k4 = (i & 127)*4;
        int g = row >> 3, jj = row & 7;
        *(float4*)&sW[row*SH_STRIDE + k4] =
            *(const float4*)&whh[(((size_t)(layer*2+dir))*2048 + g*512 + j0 + jj)*512 + k4];
    }
    if (tid < 128) sC[tid] = 0.f;
    __syncthreads();

    int r  = tid >> 3, bp = tid & 7;
    int b0 = bp, b1 = bp + 8;
    int g  = r >> 3, jj = r & 7;
    int col = dir*2048 + g*512 + j0 + jj;
    float* xout = g_xbuf[outparity];
    unsigned* cnt = &g_cnt[dir][0];
    volatile unsigned* vcnt = (volatile unsigned*)cnt;

    int t0 = dir ? (T_-1) : 0;
    float gA = g_G[(size_t)(t0*16 + b0)*NG + col];
    float gB = g_G[(size_t)(t0*16 + b1)*NG + col];

    for (int s = 0; s < T_; ++s){
        const float* hin = g_h[dir][s & 1];
        for (int i = tid; i < 2048; i += 256){
            int bb = i >> 7, k4 = (i & 127)*4;
            *(float4*)&sH[bb*SH_STRIDE + k4] = __ldcg((const float4*)&hin[bb*512 + k4]);
        }
        __syncthreads();

        // prefetch next step's G (fully hides DRAM latency)
        float ngA = 0.f, ngB = 0.f;
        if (s+1 < T_){
            int tn = dir ? (T_-2 - s) : (s+1);
            ngA = g_G[(size_t)(tn*16 + b0)*NG + col];
            ngB = g_G[(size_t)(tn*16 + b1)*NG + col];
        }

        ull aA0=0ULL, aA1=0ULL, aB0=0ULL, aB1=0ULL;
        const float* wv = &sW[r*SH_STRIDE];
        const float* hA = &sH[b0*SH_STRIDE];
        const float* hB = &sH[b1*SH_STRIDE];
        #pragma unroll 8
        for (int k = 0; k < 512; k += 8){
            ulonglong2 wa = *(const ulonglong2*)&wv[k];
            ulonglong2 wb = *(const ulonglong2*)&wv[k+4];
            ulonglong2 xa = *(const ulonglong2*)&hA[k];
            ulonglong2 xb = *(const ulonglong2*)&hA[k+4];
            ulonglong2 ya = *(const ulonglong2*)&hB[k];
            ulonglong2 yb = *(const ulonglong2*)&hB[k+4];
            fma2(aA0, wa.x, xa.x); fma2(aA0, wa.y, xa.y);
            fma2(aA1, wb.x, xb.x); fma2(aA1, wb.y, xb.y);
            fma2(aB0, wa.x, ya.x); fma2(aB0, wa.y, ya.y);
            fma2(aB1, wb.x, yb.x); fma2(aB1, wb.y, yb.y);
        }
        float2 fa0 = up2(aA0), fa1 = up2(aA1), fb0 = up2(aB0), fb1 = up2(aB1);
        sG[r*16 + b0] = gA + (fa0.x + fa0.y) + (fa1.x + fa1.y);
        sG[r*16 + b1] = gB + (fb0.x + fb0.y) + (fb1.x + fb1.y);
        gA = ngA; gB = ngB;
        __syncthreads();

        if (tid < 128){
            int jj2 = tid >> 4, b2 = tid & 15;
            float gi = sG[(0*8+jj2)*16+b2];
            float gf = sG[(1*8+jj2)*16+b2];
            float gg = sG[(2*8+jj2)*16+b2];
            float go = sG[(3*8+jj2)*16+b2];
            float c = sigf(gf)*sC[jj2*16+b2] + sigf(gi)*tanhf(gg);
            sC[jj2*16+b2] = c;
            float h = sigf(go)*tanhf(c);
            g_h[dir][(s+1)&1][b2*512 + j0 + jj2] = h;
            int t2 = dir ? (T_-1 - s) : s;
            xout[(size_t)(t2*16 + b2)*1024 + dir*512 + j0 + jj2] = h;
        }
        __syncthreads();
        if (tid == 0){
            __threadfence();
            atomicAdd(&cnt[s], 1u);
            while (vcnt[s] < 64u) { }
        }
        __syncthreads();
    }
}

// ------------------------ classifier ------------------------
__global__ void __launch_bounds__(256) k_cls(const float* __restrict__ cls_w,
                                             const float* __restrict__ cls_b, int parity){
    __shared__ float sW[L_][1024];
    __shared__ float sB[L_];
    int tid = threadIdx.x;
    for (int i = tid; i < L_*1024; i += 256) ((float*)sW)[i] = cls_w[i];
    if (tid < L_) sB[tid] = cls_b[tid];
    __syncthreads();
    int m = blockIdx.x*256 + tid;
    const float* xr = &g_xbuf[parity][(size_t)m*1024];
    float acc[L_];
    #pragma unroll
    for (int l=0;l<L_;l++) acc[l] = sB[l];
    for (int k = 0; k < 1024; k += 4){
        float4 xv = *(const float4*)&xr[k];
        #pragma unroll
        for (int l=0;l<L_;l++){
            float4 wv = *(const float4*)&sW[l][k];
            acc[l] += xv.x*wv.x + xv.y*wv.y + xv.z*wv.z + xv.w*wv.w;
        }
    }
    #pragma unroll
    for (int l=0;l<L_;l++) g_logits[m*L_ + l] = acc[l];
}

// ------------------------ CRF NLL (one block) ------------------------
__global__ void __launch_bounds__(128) k_crf(const int* __restrict__ att, const int* __restrict__ lab,
                                             const float* __restrict__ startv, const float* __restrict__ endv,
                                             const float* __restrict__ trans, float* __restrict__ out){
    __shared__ float sT[36], sS[6], sE[6];
    __shared__ float sAl[16][6];
    __shared__ float sNum[16], sLoss[16];
    int tid = threadIdx.x;
    if (tid < 36) sT[tid] = trans[tid];
    if (tid < 6){ sS[tid] = startv[tid]; sE[tid] = endv[tid]; }
    __syncthreads();

    bool isDen = tid < 96;
    bool isNum = (tid >= 96) && (tid < 112);
    int b = isDen ? tid/6 : tid-96;
    int j = tid % 6;

    float score = 0.f; int prev = 0;
    if (isDen){
        sAl[b][j] = sS[j] + g_logits[b*L_ + j];
    }
    if (isNum){
        int l0 = lab[b*T_];
        int t0 = (l0 == -100) ? 0 : l0;
        score = sS[t0] + g_logits[b*L_ + t0];
        prev = t0;
    }
    __syncthreads();

    for (int t = 1; t < T_; ++t){
        float nxt = 0.f; bool mk = false;
        if (isDen){
            mk = (att[b*T_ + t] != 0) && (lab[b*T_ + t] != -100);
            float e = g_logits[(t*16 + b)*L_ + j];
            float mx = -1e30f;
            #pragma unroll
            for (int i2=0;i2<6;i2++) mx = fmaxf(mx, sAl[b][i2] + sT[i2*6+j]);
            float ss = 0.f;
            #pragma unroll
            for (int i2=0;i2<6;i2++) ss += expf(sAl[b][i2] + sT[i2*6+j] - mx);
            nxt = mx + logf(ss) + e;
        } else if (isNum){
            int lb = lab[b*T_ + t];
            bool m = (att[b*T_ + t] != 0) && (lb != -100);
            int tt = (lb == -100) ? 0 : lb;
            if (m){
                score += sT[prev*6 + tt] + g_logits[(t*16 + b)*L_ + tt];
                prev = tt;
            }
        }
        __syncthreads();
        if (isDen && mk) sAl[b][j] = nxt;
        __syncthreads();
    }

    if (isNum) sNum[b] = score + sE[prev];
    __syncthreads();
    if (tid < 16){
        float mx = -1e30f;
        #pragma unroll
        for (int jj=0;jj<6;jj++) mx = fmaxf(mx, sAl[tid][jj] + sE[jj]);
        float ss = 0.f;
        #pragma unroll
        for (int jj=0;jj<6;jj++) ss += expf(sAl[tid][jj] + sE[jj] - mx);
        float den = mx + logf(ss);
        sLoss[tid] = den - sNum[tid];
    }
    __syncthreads();
    if (tid == 0){
        float s = 0.f;
        for (int i=0;i<16;i++) s += sLoss[i];
        out[0] = s / 16.f;
    }
}

// ------------------------ launch ------------------------
extern "C" void kernel_launch(void* const* d_in, const int* in_sizes, int n_in,
                              void* d_out, int out_size){
    const float* emb    = (const float*)d_in[0];
    const int*   att    = (const int*)  d_in[1];
    const int*   lab    = (const int*)  d_in[2];
    const float* conv_w = (const float*)d_in[3];
    const float* conv_b = (const float*)d_in[4];
    const float* bn_g   = (const float*)d_in[5];
    const float* bn_b   = (const float*)d_in[6];
    const float* bn_m   = (const float*)d_in[7];
    const float* bn_v   = (const float*)d_in[8];
    const float* wih    = (const float*)d_in[9];
    const float* whh    = (const float*)d_in[10];
    const float* bih    = (const float*)d_in[11];
    const float* bhh    = (const float*)d_in[12];
    const float* cls_w  = (const float*)d_in[13];
    const float* cls_b  = (const float*)d_in[14];
    const float* crf_s  = (const float*)d_in[15];
    const float* crf_e  = (const float*)d_in[16];
    const float* crf_t  = (const float*)d_in[17];
    float* out = (float*)d_out;

    const int RECUR_SMEM = (32*SH_STRIDE + 16*SH_STRIDE + 512 + 128) * 4;
    cudaFuncSetAttribute(k_recur, cudaFuncAttributeMaxDynamicSharedMemorySize, RECUR_SMEM);

    k_pack_w5   <<<5*E_*C_/256, 256>>>(conv_w);
    k_pack_wih  <<<3*KI*NG/256, 256>>>(wih);
    k_pack_small<<<48, 256>>>(bih, bhh, bn_g, bn_b, bn_m, bn_v, conv_b);

    k_conv<<<dim3(C_/128, M_/128), 256>>>(emb);

    for (int l = 0; l < 3; ++l){
        int inpar  = l & 1;
        int outpar = (l + 1) & 1;
        k_gemm_gates<<<dim3(NG/128, M_/128), 256>>>(l, inpar);
        k_reset<<<128, 256>>>();
        k_recur<<<128, 256, RECUR_SMEM>>>(whh, l, outpar);
    }

    k_cls<<<M_/256, 256>>>(cls_w, cls_b, 1);
    k_crf<<<1, 128>>>(att, lab, crf_s, crf_e, crf_t, out);
}

// round 9
// speedup vs baseline: 1.1257x; 1.1174x over previous
#include <cuda_runtime.h>
#include <cuda_bf16.h>
#include <math.h>
#include <cstdint>

typedef unsigned long long ull;

#define T_ 1024
#define B_ 16
#define E_ 1024
#define H_ 512
#define C_ 1024
#define L_ 6
#define M_ (T_*B_)
#define NG 4096
#define KI 1024

// ------------------------ device scratch ------------------------
__device__ float g_xbuf[2][(size_t)M_*C_];       // fp32 activations (recurrence out / classifier in)
__device__ float g_G[(size_t)M_*NG];             // input-projected gates [m][4096]
__device__ float g_W5[5*E_*C_];                  // conv weights [kk][c] (SIMT conv)
__device__ unsigned short g_Xhi[(size_t)M_*KI];  // bf16 hi plane of activations
__device__ unsigned short g_Xlo[(size_t)M_*KI];  // bf16 lo plane
__device__ unsigned short g_Whi[3][(size_t)NG*KI]; // bf16 hi of wih ([n][k] layout)
__device__ unsigned short g_Wlo[3][(size_t)NG*KI];
__device__ float g_biasG[3][NG];
__device__ float g_bnA[C_], g_bnB[C_];
__device__ float g_h[2][2][H_*B_];
__device__ unsigned g_cnt[2][T_];
__device__ float g_logits[M_*L_];

// ------------------------ helpers ------------------------
__device__ __forceinline__ ull pk2(float x){ ull r; asm("mov.b64 %0,{%1,%1};" : "=l"(r) : "f"(x)); return r; }
__device__ __forceinline__ void fma2(ull& a, ull x, ull y){ asm("fma.rn.f32x2 %0, %1, %2, %0;" : "+l"(a) : "l"(x), "l"(y)); }
__device__ __forceinline__ float2 up2(ull a){ float2 f; asm("mov.b64 {%0,%1}, %2;" : "=f"(f.x), "=f"(f.y) : "l"(a)); return f; }
__device__ __forceinline__ float sigf(float x){ return 1.f/(1.f + expf(-x)); }

__device__ __forceinline__ void split_bf(float v, unsigned short& h, unsigned short& l){
    __nv_bfloat16 hb = __float2bfloat16(v);
    h = __bfloat16_as_ushort(hb);
    l = __bfloat16_as_ushort(__float2bfloat16(v - __bfloat162float(hb)));
}

__device__ __forceinline__ unsigned smem_u32(const void* p){
    unsigned a; asm("{ .reg .u64 t; cvta.to.shared.u64 t, %1; cvt.u32.u64 %0, t; }" : "=r"(a) : "l"(p));
    return a;
}

#define LDSM4(r, a) \
    asm volatile("ldmatrix.sync.aligned.m8n8.x4.shared.b16 {%0,%1,%2,%3}, [%4];" \
        : "=r"((r)[0]),"=r"((r)[1]),"=r"((r)[2]),"=r"((r)[3]) : "r"(a))

#define MMA16816(dd, A, b0, b1) \
    asm volatile("mma.sync.aligned.m16n8k16.row.col.f32.bf16.bf16.f32 " \
        "{%0,%1,%2,%3}, {%4,%5,%6,%7}, {%8,%9}, {%0,%1,%2,%3};" \
        : "+f"((dd)[0]),"+f"((dd)[1]),"+f"((dd)[2]),"+f"((dd)[3]) \
        : "r"((A)[0]),"r"((A)[1]),"r"((A)[2]),"r"((A)[3]), "r"(b0),"r"(b1))

// ------------------------ pack / convert kernels ------------------------
__global__ void k_pack_w5(const float* __restrict__ cw){
    int idx = blockIdx.x*256 + threadIdx.x;
    int c  = idx & (C_-1);
    int kk = idx >> 10;
    int e  = kk & (E_-1);
    int dk = kk >> 10;
    g_W5[idx] = cw[((size_t)c*E_ + e)*5 + dk];
}

__global__ void k_cvt_w(const float* __restrict__ wih){
    size_t idx = (size_t)blockIdx.x*256 + threadIdx.x;   // < 3*4096*1024
    float v = wih[idx];
    unsigned short h, l; split_bf(v, h, l);
    ((unsigned short*)g_Whi)[idx] = h;
    ((unsigned short*)g_Wlo)[idx] = l;
}

__global__ void k_pack_small(const float* __restrict__ bih, const float* __restrict__ bhh,
                             const float* __restrict__ gamma, const float* __restrict__ beta,
                             const float* __restrict__ mean, const float* __restrict__ var,
                             const float* __restrict__ convb){
    int idx = blockIdx.x*256 + threadIdx.x;
    if (idx < 3*NG){
        int l = idx / NG; int n = idx - l*NG;
        int dir = n >> 11, r = n & 2047;
        int src = (l*2+dir)*2048 + r;
        ((float*)g_biasG)[idx] = bih[src] + bhh[src];
    }
    if (idx < C_){
        float s = gamma[idx] * rsqrtf(var[idx] + 1e-5f);
        g_bnA[idx] = s;
        g_bnB[idx] = s*convb[idx] + beta[idx] - mean[idx]*s;
    }
}

__global__ void k_reset(){
    int idx = blockIdx.x*256 + threadIdx.x;
    if (idx < 2*2*H_*B_) ((float*)g_h)[idx] = 0.f;
    if (idx < 2*T_) ((unsigned*)g_cnt)[idx] = 0u;
}

// ------------------------ SIMT conv-as-GEMM + BN + ReLU (bf16 hi/lo output) ------------------------
#define ROWF(i, av) { fma2(acc[i][0],av,b0v.x); fma2(acc[i][1],av,b0v.y); \
                      fma2(acc[i][2],av,b1v.x); fma2(acc[i][3],av,b1v.y); }

__global__ void __launch_bounds__(256,2) k_conv(const float* __restrict__ emb){
    __shared__ float As2[2][8][256];
    __shared__ float Bs[2][8][128];
    int tid = threadIdx.x;
    int m0 = blockIdx.y*128, n0 = blockIdx.x*128;
    int arow = tid>>1, acol = (tid&1)*4;
    int brow = tid>>5, bcol = (tid&31)*4;
    int m = m0 + arow; int t = m>>4, b = m&15;
    const float* Bp = g_W5 + (size_t)brow*C_ + n0 + bcol;

    auto fetchA = [&](int kt)->float4{
        int kk = kt*8 + acol;
        int dk = kk >> 10, e = kk & 1023;
        int tp = t + dk - 2;
        if ((unsigned)tp < 1024u)
            return *(const float4*)(emb + ((size_t)b*1024 + tp)*1024 + e);
        return make_float4(0.f,0.f,0.f,0.f);
    };
    float4 aP = fetchA(0);
    float4 bP = *(const float4*)Bp;
    ull acc[8][4];
    #pragma unroll
    for (int i=0;i<8;i++){ acc[i][0]=0ULL; acc[i][1]=0ULL; acc[i][2]=0ULL; acc[i][3]=0ULL; }
    int tx = tid&15, ty = tid>>4;
    {
        *(ull*)&As2[0][acol+0][2*arow] = pk2(aP.x);
        *(ull*)&As2[0][acol+1][2*arow] = pk2(aP.y);
        *(ull*)&As2[0][acol+2][2*arow] = pk2(aP.z);
        *(ull*)&As2[0][acol+3][2*arow] = pk2(aP.w);
        *(float4*)&Bs[0][brow][bcol] = bP;
    }
    __syncthreads();

    for (int kt=0; kt<640; ++kt){
        int buf = kt & 1;
        if (kt+1 < 640){ aP = fetchA(kt+1); bP = *(const float4*)(Bp + (size_t)(kt+1)*8*C_); }
        #pragma unroll
        for (int k = 0; k < 8; k++){
            ulonglong2 aA = *(const ulonglong2*)&As2[buf][k][ty*8];
            ulonglong2 aB = *(const ulonglong2*)&As2[buf][k][ty*8+4];
            ulonglong2 aC = *(const ulonglong2*)&As2[buf][k][128+ty*8];
            ulonglong2 aD = *(const ulonglong2*)&As2[buf][k][128+ty*8+4];
            ulonglong2 b0v = *(const ulonglong2*)&Bs[buf][k][tx*4];
            ulonglong2 b1v = *(const ulonglong2*)&Bs[buf][k][64+tx*4];
            ROWF(0, aA.x) ROWF(1, aA.y) ROWF(2, aB.x) ROWF(3, aB.y)
            ROWF(4, aC.x) ROWF(5, aC.y) ROWF(6, aD.x) ROWF(7, aD.y)
        }
        if (kt+1 < 640){
            int nb = buf^1;
            *(ull*)&As2[nb][acol+0][2*arow] = pk2(aP.x);
            *(ull*)&As2[nb][acol+1][2*arow] = pk2(aP.y);
            *(ull*)&As2[nb][acol+2][2*arow] = pk2(aP.z);
            *(ull*)&As2[nb][acol+3][2*arow] = pk2(aP.w);
            *(float4*)&Bs[nb][brow][bcol] = bP;
        }
        __syncthreads();
    }
    int c0 = n0 + tx*4;
    float4 A0 = *(const float4*)&g_bnA[c0];    float4 Bb0 = *(const float4*)&g_bnB[c0];
    float4 A1 = *(const float4*)&g_bnA[c0+64]; float4 Bb1 = *(const float4*)&g_bnB[c0+64];
    #pragma unroll
    for (int i=0;i<8;i++){
        int mr = m0 + (i<4 ? ty*4+i : 64+ty*4+(i-4));
        float2 p0=up2(acc[i][0]), p1=up2(acc[i][1]), p2=up2(acc[i][2]), p3=up2(acc[i][3]);
        float v[8];
        v[0]=fmaxf(p0.x*A0.x+Bb0.x,0.f); v[1]=fmaxf(p0.y*A0.y+Bb0.y,0.f);
        v[2]=fmaxf(p1.x*A0.z+Bb0.z,0.f); v[3]=fmaxf(p1.y*A0.w+Bb0.w,0.f);
        v[4]=fmaxf(p2.x*A1.x+Bb1.x,0.f); v[5]=fmaxf(p2.y*A1.y+Bb1.y,0.f);
        v[6]=fmaxf(p3.x*A1.z+Bb1.z,0.f); v[7]=fmaxf(p3.y*A1.w+Bb1.w,0.f);
        ushort4 hi0, lo0, hi1, lo1;
        split_bf(v[0], hi0.x, lo0.x); split_bf(v[1], hi0.y, lo0.y);
        split_bf(v[2], hi0.z, lo0.z); split_bf(v[3], hi0.w, lo0.w);
        split_bf(v[4], hi1.x, lo1.x); split_bf(v[5], hi1.y, lo1.y);
        split_bf(v[6], hi1.z, lo1.z); split_bf(v[7], hi1.w, lo1.w);
        *(ushort4*)&g_Xhi[(size_t)mr*1024 + c0]      = hi0;
        *(ushort4*)&g_Xlo[(size_t)mr*1024 + c0]      = lo0;
        *(ushort4*)&g_Xhi[(size_t)mr*1024 + c0 + 64] = hi1;
        *(ushort4*)&g_Xlo[(size_t)mr*1024 + c0 + 64] = lo1;
    }
}

// ------------------------ mma.sync split-bf16 gate GEMM ------------------------
// G[m][n] = sum_k X[m][k]*W[n][k] + bias[n], via Ahi*Bhi + Ahi*Blo + Alo*Bhi.
// CTA 128x128, K chunks of 32, cp.async double buffer, 8 warps of 32x64.
// Smem plane: 128 rows x 80B (32 bf16 data + pad) => ldmatrix conflict-free.
#define PLANE_B 10240            // 128*80
#define STAGE_B (4*PLANE_B)      // 40960
#define GT_SMEM (2*STAGE_B)      // 81920

__global__ void __launch_bounds__(256) k_gate(int layer){
    extern __shared__ char smem[];
    unsigned sbase = smem_u32(smem);
    int tid = threadIdx.x;
    int wid = tid >> 5, lane = tid & 31;
    int m0 = blockIdx.y*128, n0 = blockIdx.x*128;

    const unsigned short* srcs[4] = {
        g_Xhi + (size_t)m0*1024,
        g_Xlo + (size_t)m0*1024,
        g_Whi[layer] + (size_t)n0*1024,
        g_Wlo[layer] + (size_t)n0*1024
    };

    auto prefetch = [&](int kc, int stg){
        unsigned sb = sbase + stg*STAGE_B;
        #pragma unroll
        for (int it = 0; it < 8; ++it){
            int i = it*256 + tid;              // 0..2047
            int p = i >> 9, rem = i & 511;
            int row = rem >> 2, c = rem & 3;
            unsigned sa = sb + p*PLANE_B + row*80 + c*16;
            const void* ga = srcs[p] + (size_t)row*1024 + kc*32 + c*8;
            asm volatile("cp.async.cg.shared.global [%0], [%1], 16;" :: "r"(sa), "l"(ga) : "memory");
        }
        asm volatile("cp.async.commit_group;" ::: "memory");
    };

    int wm = wid >> 1, wn = wid & 1;
    float d[2][8][4];
    #pragma unroll
    for (int mi=0;mi<2;++mi)
        #pragma unroll
        for (int ni=0;ni<8;++ni)
            #pragma unroll
            for (int q=0;q<4;++q) d[mi][ni][q] = 0.f;

    prefetch(0, 0);

    for (int kt = 0; kt < 32; ++kt){
        int stg = kt & 1;
        asm volatile("cp.async.wait_group 0;" ::: "memory");
        __syncthreads();
        if (kt + 1 < 32) prefetch(kt + 1, stg ^ 1);

        unsigned sb  = sbase + stg*STAGE_B;
        unsigned aHi = sb,            aLo = sb + PLANE_B;
        unsigned bHi = sb + 2*PLANE_B, bLo = sb + 3*PLANE_B;

        #pragma unroll
        for (int kh = 0; kh < 2; ++kh){
            unsigned Ah[2][4], Al[2][4];
            #pragma unroll
            for (int mi = 0; mi < 2; ++mi){
                int row = wm*32 + mi*16 + (lane & 15);
                int ch  = kh*2 + (lane >> 4);
                unsigned off = row*80 + ch*16;
                LDSM4(Ah[mi], aHi + off);
                LDSM4(Al[mi], aLo + off);
            }
            unsigned Bh[4][4], Bl[4][4];
            #pragma unroll
            for (int pr = 0; pr < 4; ++pr){
                int row = wn*64 + pr*16 + (lane & 7) + ((lane >> 4) << 3);
                int ch  = kh*2 + ((lane >> 3) & 1);
                unsigned off = row*80 + ch*16;
                LDSM4(Bh[pr], bHi + off);
                LDSM4(Bl[pr], bLo + off);
            }
            #pragma unroll
            for (int mi = 0; mi < 2; ++mi){
                #pragma unroll
                for (int pr = 0; pr < 4; ++pr){
                    MMA16816(d[mi][2*pr],   Ah[mi], Bh[pr][0], Bh[pr][1]);
                    MMA16816(d[mi][2*pr],   Ah[mi], Bl[pr][0], Bl[pr][1]);
                    MMA16816(d[mi][2*pr],   Al[mi], Bh[pr][0], Bh[pr][1]);
                    MMA16816(d[mi][2*pr+1], Ah[mi], Bh[pr][2], Bh[pr][3]);
                    MMA16816(d[mi][2*pr+1], Ah[mi], Bl[pr][2], Bl[pr][3]);
                    MMA16816(d[mi][2*pr+1], Al[mi], Bh[pr][2], Bh[pr][3]);
                }
            }
        }
    }

    // epilogue: D + bias -> g_G
    int qr = lane >> 2, qc = lane & 3;
    #pragma unroll
    for (int mi = 0; mi < 2; ++mi){
        #pragma unroll
        for (int ni = 0; ni < 8; ++ni){
            int col = n0 + wn*64 + ni*8 + qc*2;
            float2 bq = *(const float2*)&g_biasG[layer][col];
            int r0 = m0 + wm*32 + mi*16 + qr;
            float2 v0 = make_float2(d[mi][ni][0] + bq.x, d[mi][ni][1] + bq.y);
            *(float2*)&g_G[(size_t)r0*NG + col] = v0;
            float2 v1 = make_float2(d[mi][ni][2] + bq.x, d[mi][ni][3] + bq.y);
            *(float2*)&g_G[(size_t)(r0+8)*NG + col] = v1;
        }
    }
}

// ------------------------ persistent BiLSTM recurrence ------------------------
#define SH_STRIDE 516
__global__ void __launch_bounds__(256) k_recur(const float* __restrict__ whh, int layer, int outparity){
    extern __shared__ float smemf[];
    float* sW = smemf;
    float* sH = sW + 32*SH_STRIDE;
    float* sG = sH + 16*SH_STRIDE;
    float* sC = sG + 512;
    int tid = threadIdx.x;
    int dir = blockIdx.x >> 6;
    int bid = blockIdx.x & 63;
    int j0 = bid*8;

    for (int i = tid; i < 32*128; i += 256){
        int row = i >> 7, k4 = (i & 127)*4;
        int g = row >> 3, jj = row & 7;
        *(float4*)&sW[row*SH_STRIDE + k4] =
            *(const float4*)&whh[(((size_t)(layer*2+dir))*2048 + g*512 + j0 + jj)*512 + k4];
    }
    if (tid < 128) sC[tid] = 0.f;
    __syncthreads();

    int r  = tid >> 3, bp = tid & 7;
    int b0 = bp, b1 = bp + 8;
    int g  = r >> 3, jj = r & 7;
    int col = dir*2048 + g*512 + j0 + jj;
    float* xout = g_xbuf[outparity];
    unsigned* cnt = &g_cnt[dir][0];
    volatile unsigned* vcnt = (volatile unsigned*)cnt;

    int t0 = dir ? (T_-1) : 0;
    float gA = g_G[(size_t)(t0*16 + b0)*NG + col];
    float gB = g_G[(size_t)(t0*16 + b1)*NG + col];

    for (int s = 0; s < T_; ++s){
        const float* hin = g_h[dir][s & 1];
        for (int i = tid; i < 2048; i += 256){
            int bb = i >> 7, k4 = (i & 127)*4;
            *(float4*)&sH[bb*SH_STRIDE + k4] = __ldcg((const float4*)&hin[bb*512 + k4]);
        }
        __syncthreads();

        float ngA = 0.f, ngB = 0.f;
        if (s+1 < T_){
            int tn = dir ? (T_-2 - s) : (s+1);
            ngA = g_G[(size_t)(tn*16 + b0)*NG + col];
            ngB = g_G[(size_t)(tn*16 + b1)*NG + col];
        }

        ull aA0=0ULL, aA1=0ULL, aB0=0ULL, aB1=0ULL;
        const float* wv = &sW[r*SH_STRIDE];
        const float* hA = &sH[b0*SH_STRIDE];
        const float* hB = &sH[b1*SH_STRIDE];
        #pragma unroll 8
        for (int k = 0; k < 512; k += 8){
            ulonglong2 wa = *(const ulonglong2*)&wv[k];
            ulonglong2 wb = *(const ulonglong2*)&wv[k+4];
            ulonglong2 xa = *(const ulonglong2*)&hA[k];
            ulonglong2 xb = *(const ulonglong2*)&hA[k+4];
            ulonglong2 ya = *(const ulonglong2*)&hB[k];
            ulonglong2 yb = *(const ulonglong2*)&hB[k+4];
            fma2(aA0, wa.x, xa.x); fma2(aA0, wa.y, xa.y);
            fma2(aA1, wb.x, xb.x); fma2(aA1, wb.y, xb.y);
            fma2(aB0, wa.x, ya.x); fma2(aB0, wa.y, ya.y);
            fma2(aB1, wb.x, yb.x); fma2(aB1, wb.y, yb.y);
        }
        float2 fa0 = up2(aA0), fa1 = up2(aA1), fb0 = up2(aB0), fb1 = up2(aB1);
        sG[r*16 + b0] = gA + (fa0.x + fa0.y) + (fa1.x + fa1.y);
        sG[r*16 + b1] = gB + (fb0.x + fb0.y) + (fb1.x + fb1.y);
        gA = ngA; gB = ngB;
        __syncthreads();

        if (tid < 128){
            int jj2 = tid >> 4, b2 = tid & 15;
            float gi = sG[(0*8+jj2)*16+b2];
            float gf = sG[(1*8+jj2)*16+b2];
            float gg = sG[(2*8+jj2)*16+b2];
            float go = sG[(3*8+jj2)*16+b2];
            float c = sigf(gf)*sC[jj2*16+b2] + sigf(gi)*tanhf(gg);
            sC[jj2*16+b2] = c;
            float h = sigf(go)*tanhf(c);
            g_h[dir][(s+1)&1][b2*512 + j0 + jj2] = h;
            int t2 = dir ? (T_-1 - s) : s;
            size_t mo = (size_t)(t2*16 + b2)*1024 + dir*512 + j0 + jj2;
            xout[mo] = h;
            unsigned short hh, hl; split_bf(h, hh, hl);
            g_Xhi[mo] = hh;
            g_Xlo[mo] = hl;
        }
        __syncthreads();
        if (tid == 0){
            __threadfence();
            atomicAdd(&cnt[s], 1u);
            while (vcnt[s] < 64u) { }
        }
        __syncthreads();
    }
}

// ------------------------ classifier ------------------------
__global__ void __launch_bounds__(256) k_cls(const float* __restrict__ cls_w,
                                             const float* __restrict__ cls_b, int parity){
    __shared__ float sW[L_][1024];
    __shared__ float sB[L_];
    int tid = threadIdx.x;
    for (int i = tid; i < L_*1024; i += 256) ((float*)sW)[i] = cls_w[i];
    if (tid < L_) sB[tid] = cls_b[tid];
    __syncthreads();
    int m = blockIdx.x*256 + tid;
    const float* xr = &g_xbuf[parity][(size_t)m*1024];
    float acc[L_];
    #pragma unroll
    for (int l=0;l<L_;l++) acc[l] = sB[l];
    for (int k = 0; k < 1024; k += 4){
        float4 xv = *(const float4*)&xr[k];
        #pragma unroll
        for (int l=0;l<L_;l++){
            float4 wv = *(const float4*)&sW[l][k];
            acc[l] += xv.x*wv.x + xv.y*wv.y + xv.z*wv.z + xv.w*wv.w;
        }
    }
    #pragma unroll
    for (int l=0;l<L_;l++) g_logits[m*L_ + l] = acc[l];
}

// ------------------------ CRF NLL (one block) ------------------------
__global__ void __launch_bounds__(128) k_crf(const int* __restrict__ att, const int* __restrict__ lab,
                                             const float* __restrict__ startv, const float* __restrict__ endv,
                                             const float* __restrict__ trans, float* __restrict__ out){
    __shared__ float sT[36], sS[6], sE[6];
    __shared__ float sAl[16][6];
    __shared__ float sNum[16], sLoss[16];
    int tid = threadIdx.x;
    if (tid < 36) sT[tid] = trans[tid];
    if (tid < 6){ sS[tid] = startv[tid]; sE[tid] = endv[tid]; }
    __syncthreads();

    bool isDen = tid < 96;
    bool isNum = (tid >= 96) && (tid < 112);
    int b = isDen ? tid/6 : tid-96;
    int j = tid % 6;

    float score = 0.f; int prev = 0;
    if (isDen) sAl[b][j] = sS[j] + g_logits[b*L_ + j];
    if (isNum){
        int l0 = lab[b*T_];
        int t0 = (l0 == -100) ? 0 : l0;
        score = sS[t0] + g_logits[b*L_ + t0];
        prev = t0;
    }
    __syncthreads();

    for (int t = 1; t < T_; ++t){
        float nxt = 0.f; bool mk = false;
        if (isDen){
            mk = (att[b*T_ + t] != 0) && (lab[b*T_ + t] != -100);
            float e = g_logits[(t*16 + b)*L_ + j];
            float mx = -1e30f;
            #pragma unroll
            for (int i2=0;i2<6;i2++) mx = fmaxf(mx, sAl[b][i2] + sT[i2*6+j]);
            float ss = 0.f;
            #pragma unroll
            for (int i2=0;i2<6;i2++) ss += expf(sAl[b][i2] + sT[i2*6+j] - mx);
            nxt = mx + logf(ss) + e;
        } else if (isNum){
            int lb = lab[b*T_ + t];
            bool m = (att[b*T_ + t] != 0) && (lb != -100);
            int tt = (lb == -100) ? 0 : lb;
            if (m){
                score += sT[prev*6 + tt] + g_logits[(t*16 + b)*L_ + tt];
                prev = tt;
            }
        }
        __syncthreads();
        if (isDen && mk) sAl[b][j] = nxt;
        __syncthreads();
    }

    if (isNum) sNum[b] = score + sE[prev];
    __syncthreads();
    if (tid < 16){
        float mx = -1e30f;
        #pragma unroll
        for (int jj=0;jj<6;jj++) mx = fmaxf(mx, sAl[tid][jj] + sE[jj]);
        float ss = 0.f;
        #pragma unroll
        for (int jj=0;jj<6;jj++) ss += expf(sAl[tid][jj] + sE[jj] - mx);
        float den = mx + logf(ss);
        sLoss[tid] = den - sNum[tid];
    }
    __syncthreads();
    if (tid == 0){
        float s = 0.f;
        for (int i=0;i<16;i++) s += sLoss[i];
        out[0] = s / 16.f;
    }
}

// ------------------------ launch ------------------------
extern "C" void kernel_launch(void* const* d_in, const int* in_sizes, int n_in,
                              void* d_out, int out_size){
    const float* emb    = (const float*)d_in[0];
    const int*   att    = (const int*)  d_in[1];
    const int*   lab    = (const int*)  d_in[2];
    const float* conv_w = (const float*)d_in[3];
    const float* conv_b = (const float*)d_in[4];
    const float* bn_g   = (const float*)d_in[5];
    const float* bn_b   = (const float*)d_in[6];
    const float* bn_m   = (const float*)d_in[7];
    const float* bn_v   = (const float*)d_in[8];
    const float* wih    = (const float*)d_in[9];
    const float* whh    = (const float*)d_in[10];
    const float* bih    = (const float*)d_in[11];
    const float* bhh    = (const float*)d_in[12];
    const float* cls_w  = (const float*)d_in[13];
    const float* cls_b  = (const float*)d_in[14];
    const float* crf_s  = (const float*)d_in[15];
    const float* crf_e  = (const float*)d_in[16];
    const float* crf_t  = (const float*)d_in[17];
    float* out = (float*)d_out;

    const int RECUR_SMEM = (32*SH_STRIDE + 16*SH_STRIDE + 512 + 128) * 4;
    cudaFuncSetAttribute(k_recur, cudaFuncAttributeMaxDynamicSharedMemorySize, RECUR_SMEM);
    cudaFuncSetAttribute(k_gate,  cudaFuncAttributeMaxDynamicSharedMemorySize, GT_SMEM);

    k_pack_w5   <<<5*E_*C_/256, 256>>>(conv_w);
    k_cvt_w     <<<3*NG*KI/256, 256>>>(wih);
    k_pack_small<<<48, 256>>>(bih, bhh, bn_g, bn_b, bn_m, bn_v, conv_b);

    k_conv<<<dim3(C_/128, M_/128), 256>>>(emb);

    for (int l = 0; l < 3; ++l){
        int outpar = (l + 1) & 1;
        k_gate<<<dim3(NG/128, M_/128), 256, GT_SMEM>>>(l);
        k_reset<<<128, 256>>>();
        k_recur<<<128, 256, RECUR_SMEM>>>(whh, l, outpar);
    }

    k_cls<<<M_/256, 256>>>(cls_w, cls_b, 1);
    k_crf<<<1, 128>>>(att, lab, crf_s, crf_e, crf_t, out);
}